// round 2
// baseline (speedup 1.0000x reference)
#include <cuda_runtime.h>
#include <cuda_bf16.h>
#include <math.h>

#define N_NODES 50000
#define N_EDGES 800000
#define N_FEAT  128
#define DIM     32
#define N_GRAPHS 500
#define N_CLASSES 2

// ---------------- scratch (no allocations allowed) ----------------
__device__ float g_y[N_NODES * DIM];     // x @ w_rel
__device__ float g_z[N_NODES * DIM];     // x @ w_root
__device__ float g_agg[N_NODES * DIM];   // segment_sum of weighted y
__device__ float g_pooled[N_GRAPHS * DIM];
__device__ int   g_idx_is64;             // 1 if index buffers are int64

// ---------------- kernel 0: detect index dtype ----------------
// If edge_index is int64 (little-endian) every odd 32-bit word is the high
// word of a value < 50000 -> 0. With int32 data those words are random ids.
__global__ void detect_kernel(const int* __restrict__ ei_raw) {
    __shared__ int s_any;
    if (threadIdx.x == 0) s_any = 0;
    __syncthreads();
    // check 512 high-word candidates
    int v = ei_raw[threadIdx.x * 2 + 1];
    if (v != 0) atomicOr(&s_any, 1);
    __syncthreads();
    if (threadIdx.x == 0) g_idx_is64 = s_any ? 0 : 1;
}

// ---------------- kernel 1: projection + zero scratch ----------------
// block = 256 threads = 8 warps = 8 nodes. grid = 6250.
__global__ void proj_kernel(const float* __restrict__ x,
                            const float* __restrict__ w_rel,
                            const float* __restrict__ w_root) {
    __shared__ float s_rel[N_FEAT * DIM];
    __shared__ float s_root[N_FEAT * DIM];
    int tid = threadIdx.x;
    for (int i = tid; i < N_FEAT * DIM; i += 256) {
        s_rel[i]  = w_rel[i];
        s_root[i] = w_root[i];
    }
    __syncthreads();

    // zero pooled with the first blocks
    int gtid = blockIdx.x * 256 + tid;
    if (gtid < N_GRAPHS * DIM) g_pooled[gtid] = 0.0f;

    int warp = tid >> 5;
    int lane = tid & 31;
    int node = blockIdx.x * 8 + warp;
    if (node >= N_NODES) return;

    const float* xr = x + (size_t)node * N_FEAT;
    float xv0 = xr[lane];
    float xv1 = xr[32 + lane];
    float xv2 = xr[64 + lane];
    float xv3 = xr[96 + lane];

    float acc_y = 0.0f, acc_z = 0.0f;
#pragma unroll
    for (int k = 0; k < 32; k++) {
        float a = __shfl_sync(0xffffffffu, xv0, k);
        acc_y = fmaf(a, s_rel[k * DIM + lane], acc_y);
        acc_z = fmaf(a, s_root[k * DIM + lane], acc_z);
    }
#pragma unroll
    for (int k = 0; k < 32; k++) {
        float a = __shfl_sync(0xffffffffu, xv1, k);
        acc_y = fmaf(a, s_rel[(32 + k) * DIM + lane], acc_y);
        acc_z = fmaf(a, s_root[(32 + k) * DIM + lane], acc_z);
    }
#pragma unroll
    for (int k = 0; k < 32; k++) {
        float a = __shfl_sync(0xffffffffu, xv2, k);
        acc_y = fmaf(a, s_rel[(64 + k) * DIM + lane], acc_y);
        acc_z = fmaf(a, s_root[(64 + k) * DIM + lane], acc_z);
    }
#pragma unroll
    for (int k = 0; k < 32; k++) {
        float a = __shfl_sync(0xffffffffu, xv3, k);
        acc_y = fmaf(a, s_rel[(96 + k) * DIM + lane], acc_y);
        acc_z = fmaf(a, s_root[(96 + k) * DIM + lane], acc_z);
    }

    g_y[node * DIM + lane]   = acc_y;
    g_z[node * DIM + lane]   = acc_z;
    g_agg[node * DIM + lane] = 0.0f;
}

// ---------------- kernel 2: edge scatter ----------------
// 8 threads per edge, each owns 4 consecutive output columns (float4).
__global__ void edge_kernel(const int* __restrict__ ei_raw,
                            const float* __restrict__ ew) {
    int t = blockIdx.x * blockDim.x + threadIdx.x;
    int e = t >> 3;
    if (e >= N_EDGES) return;
    int sub = t & 7;

    int src, dst;
    if (g_idx_is64) {
        src = ei_raw[2 * e];
        dst = ei_raw[2 * (N_EDGES + e)];
    } else {
        src = ei_raw[e];
        dst = ei_raw[N_EDGES + e];
    }
    if ((unsigned)src >= N_NODES || (unsigned)dst >= N_NODES) return;

    float w = ew[e];
    float4 v = reinterpret_cast<const float4*>(g_y)[src * 8 + sub];
    float4* dp = reinterpret_cast<float4*>(g_agg) + dst * 8 + sub;
    asm volatile("red.global.add.v4.f32 [%0], {%1,%2,%3,%4};"
                 :: "l"(dp), "f"(v.x * w), "f"(v.y * w), "f"(v.z * w), "f"(v.w * w)
                 : "memory");
}

// ---------------- kernel 3: node activation + graph pooling ----------------
__global__ void node_kernel(const float* __restrict__ b_rel,
                            const int* __restrict__ batch_raw) {
    int t = blockIdx.x * blockDim.x + threadIdx.x;
    if (t >= N_NODES * 8) return;
    int n = t >> 3;
    int sub = t & 7;

    float4 a  = reinterpret_cast<const float4*>(g_agg)[n * 8 + sub];
    float4 zz = reinterpret_cast<const float4*>(g_z)[n * 8 + sub];
    float4 b  = reinterpret_cast<const float4*>(b_rel)[sub];

    float4 h;
    h.x = fmaxf(a.x + zz.x + b.x, 0.0f);
    h.y = fmaxf(a.y + zz.y + b.y, 0.0f);
    h.z = fmaxf(a.z + zz.z + b.z, 0.0f);
    h.w = fmaxf(a.w + zz.w + b.w, 0.0f);

    int g = g_idx_is64 ? batch_raw[2 * n] : batch_raw[n];
    if ((unsigned)g >= N_GRAPHS) return;
    float4* dp = reinterpret_cast<float4*>(g_pooled) + g * 8 + sub;
    asm volatile("red.global.add.v4.f32 [%0], {%1,%2,%3,%4};"
                 :: "l"(dp), "f"(h.x), "f"(h.y), "f"(h.z), "f"(h.w)
                 : "memory");
}

// ---------------- kernel 4: head MLP + log_softmax ----------------
// one warp (block of 32) per graph
__global__ void head_kernel(const float* __restrict__ w_fc1,
                            const float* __restrict__ b_fc1,
                            const float* __restrict__ w_fc2,
                            const float* __restrict__ b_fc2,
                            float* __restrict__ out) {
    __shared__ float sp[DIM];
    __shared__ float sh2[DIM];
    int g = blockIdx.x;
    int lane = threadIdx.x;

    sp[lane] = g_pooled[g * DIM + lane];
    __syncwarp();

    float acc = b_fc1[lane];
#pragma unroll
    for (int j = 0; j < DIM; j++)
        acc = fmaf(sp[j], w_fc1[j * DIM + lane], acc);
    sh2[lane] = fmaxf(acc, 0.0f);
    __syncwarp();

    if (lane == 0) {
        float l0 = b_fc2[0], l1 = b_fc2[1];
#pragma unroll
        for (int k = 0; k < DIM; k++) {
            l0 = fmaf(sh2[k], w_fc2[k * 2 + 0], l0);
            l1 = fmaf(sh2[k], w_fc2[k * 2 + 1], l1);
        }
        float m = fmaxf(l0, l1);
        float lse = m + logf(expf(l0 - m) + expf(l1 - m));
        out[g * 2 + 0] = l0 - lse;
        out[g * 2 + 1] = l1 - lse;
    }
}

extern "C" void kernel_launch(void* const* d_in, const int* in_sizes, int n_in,
                              void* d_out, int out_size) {
    const float* x      = (const float*)d_in[0];
    const float* ew     = (const float*)d_in[1];
    const float* w_rel  = (const float*)d_in[2];
    const float* b_rel  = (const float*)d_in[3];
    const float* w_root = (const float*)d_in[4];
    const float* w_fc1  = (const float*)d_in[5];
    const float* b_fc1  = (const float*)d_in[6];
    const float* w_fc2  = (const float*)d_in[7];
    const float* b_fc2  = (const float*)d_in[8];
    const int*   ei     = (const int*)d_in[9];
    const int*   batch  = (const int*)d_in[10];
    float* out = (float*)d_out;

    detect_kernel<<<1, 256>>>(ei);
    proj_kernel<<<N_NODES / 8, 256>>>(x, w_rel, w_root);
    edge_kernel<<<(N_EDGES * 8) / 256, 256>>>(ei, ew);
    node_kernel<<<(N_NODES * 8 + 255) / 256, 256>>>(b_rel, batch);
    head_kernel<<<N_GRAPHS, 32>>>(w_fc1, b_fc1, w_fc2, b_fc2, out);
}